// round 16
// baseline (speedup 1.0000x reference)
#include <cuda_runtime.h>
#include <cstdint>
#include <cfloat>

// Problem constants
#define F 4096      // nb_features
#define C 64        // coord dim
#define B 1024      // batch
#define K 16        // nb_neighbors
#define J (F*K + 1) // 65537 gathered columns

// Scratch (no allocations allowed; __device__ globals are the sanctioned path)
__device__ float g_sq[F];
__device__ int   g_cols[J];
__device__ float g_d2[(size_t)F * F];   // 64 MB distance-squared matrix (L2-resident)

__device__ __forceinline__ bool lexlt(float d, int g, float v, int i) {
    return (d < v) || (d == v && g < i);
}

__device__ __forceinline__ unsigned long long fma2p(unsigned long long a,
                                                    unsigned long long b,
                                                    unsigned long long c) {
    unsigned long long d;
    asm("fma.rn.f32x2 %0, %1, %2, %3;" : "=l"(d) : "l"(a), "l"(b), "l"(c));
    return d;
}
__device__ __forceinline__ float lo32(unsigned long long v) {
    return __uint_as_float((unsigned)v);
}
__device__ __forceinline__ float hi32(unsigned long long v) {
    return __uint_as_float((unsigned)(v >> 32));
}

// ---------------------------------------------------------------------------
// Kernel 1: per-feature squared norms (UNFUSED mul+add, sequential — matches
// the reference's square+reduce rounding; rel_err is exactly 0 with this).
// ---------------------------------------------------------------------------
__global__ __launch_bounds__(256) void k_sq(const float* __restrict__ coord) {
    int f = blockIdx.x * 256 + threadIdx.x;
    float s = 0.f;
#pragma unroll
    for (int c = 0; c < C; ++c) {
        float x = coord[c * F + f];
        s = __fadd_rn(s, __fmul_rn(x, x));
    }
    g_sq[f] = s;
}

// ---------------------------------------------------------------------------
// Kernel 2: distance GEMM -> g_d2, ROW-PAIR-PACKED f32x2: a-pairs are natural
// u64 loads from s_f (consecutive rows adjacent), only b duplicated (4 movs
// per c instead of 4-per-8-FFMA2). 8 rows x 4 g micro-tile, 16 FFMA2 per c.
// Per-(f,g) accumulation chain unchanged (bit-exact vs scalar).
//   Grid: 64 row-tiles x 4 g-quarters = 256 CTAs, 256 threads.
//   CTA tile: 64 rows x 1024 g, inner g tiles of 128. Dynamic smem ~49 KB.
// ---------------------------------------------------------------------------
#define ROWS_CTA 64
#define GW       1024
#define TGG      128
#define NT       (GW / TGG)   // 8

#define OFF_F    0                           // 64c x 64r = 4096 floats
#define OFF_SQF  (OFF_F + C * ROWS_CTA)      // 64
#define OFF_G    (OFF_SQF + ROWS_CTA)        // 64c x 128g = 8192
#define OFF_SQG  (OFF_G + C * TGG)           // 128
#define SMEM_DIST_FLOATS (OFF_SQG + TGG)
#define SMEM_DIST_BYTES  (SMEM_DIST_FLOATS * 4)   // 49,920 B

__global__ __launch_bounds__(256) void k_dist(const float* __restrict__ coord) {
    extern __shared__ float sm[];
    float* s_f   = sm + OFF_F;
    float* s_sqf = sm + OFF_SQF;
    float* s_g   = sm + OFF_G;
    float* s_sqg = sm + OFF_SQG;

    const int tid  = threadIdx.x;
    const int lane = tid & 31;
    const int w    = tid >> 5;           // warp id: rows w*8 .. w*8+7
    const int f0   = (blockIdx.x >> 2) * ROWS_CTA;
    const int g0   = (blockIdx.x & 3) * GW;

    // stage f tile: s_f[c*64 + r] = coord[c][f0+r]
    for (int idx = tid; idx < (C * ROWS_CTA) / 4; idx += 256) {
        int c = idx >> 4, r4 = (idx & 15) * 4;
        *(float4*)(s_f + c * ROWS_CTA + r4) = *(const float4*)(coord + c * F + f0 + r4);
    }
    if (tid < ROWS_CTA / 4)
        *(float4*)(s_sqf + tid * 4) = *(const float4*)(g_sq + f0 + tid * 4);

    for (int t = 0; t < NT; ++t) {
        const int gb = g0 + t * TGG;
        __syncthreads();
        for (int idx = tid; idx < (C * TGG) / 4; idx += 256) {
            int c = idx >> 5, o4 = (idx & 31) * 4;
            *(float4*)(s_g + c * TGG + o4) = *(const float4*)(coord + c * F + gb + o4);
        }
        if (tid < TGG / 4)
            *(float4*)(s_sqg + tid * 4) = *(const float4*)(g_sq + gb + tid * 4);
        __syncthreads();

        // acc qPE: rowpair P (rows 2P,2P+1 of this warp's 8), g e = lane*4+E
        unsigned long long q00 = 0, q01 = 0, q02 = 0, q03 = 0;
        unsigned long long q10 = 0, q11 = 0, q12 = 0, q13 = 0;
        unsigned long long q20 = 0, q21 = 0, q22 = 0, q23 = 0;
        unsigned long long q30 = 0, q31 = 0, q32 = 0, q33 = 0;

        const float* fp = s_f + w * 8;
        const float* gp = s_g + lane * 4;
#pragma unroll 2
        for (int c = 0; c < C; ++c) {
            // a: rows packed naturally as u64 pairs (broadcast within warp)
            ulonglong2 a01 = *(const ulonglong2*)(fp + c * ROWS_CTA);      // pairs (0,1),(2,3)
            ulonglong2 a23 = *(const ulonglong2*)(fp + c * ROWS_CTA + 4);  // pairs (4,5),(6,7)
            float4 b = *(const float4*)(gp + c * TGG);                     // 4 g, contiguous
            unsigned long long bx, by, bz, bw;
            asm("mov.b64 %0,{%1,%1};" : "=l"(bx) : "r"(__float_as_uint(b.x)));
            asm("mov.b64 %0,{%1,%1};" : "=l"(by) : "r"(__float_as_uint(b.y)));
            asm("mov.b64 %0,{%1,%1};" : "=l"(bz) : "r"(__float_as_uint(b.z)));
            asm("mov.b64 %0,{%1,%1};" : "=l"(bw) : "r"(__float_as_uint(b.w)));
            q00 = fma2p(a01.x, bx, q00); q01 = fma2p(a01.x, by, q01);
            q02 = fma2p(a01.x, bz, q02); q03 = fma2p(a01.x, bw, q03);
            q10 = fma2p(a01.y, bx, q10); q11 = fma2p(a01.y, by, q11);
            q12 = fma2p(a01.y, bz, q12); q13 = fma2p(a01.y, bw, q13);
            q20 = fma2p(a23.x, bx, q20); q21 = fma2p(a23.x, by, q21);
            q22 = fma2p(a23.x, bz, q22); q23 = fma2p(a23.x, bw, q23);
            q30 = fma2p(a23.y, bx, q30); q31 = fma2p(a23.y, by, q31);
            q32 = fma2p(a23.y, bz, q32); q33 = fma2p(a23.y, bw, q33);
        }

        float4 sg = *(const float4*)(s_sqg + lane * 4);
        const float* sfp = s_sqf + w * 8;
        float* obase = g_d2 + (size_t)(f0 + w * 8) * F + gb + lane * 4;
        // row 2P uses lo32 of qP*, row 2P+1 uses hi32
#define FIN_PAIR(Q0, Q1, Q2, Q3, P)                                            \
        {                                                                      \
            float sfl = sfp[2 * (P)];                                          \
            float sfh = sfp[2 * (P) + 1];                                      \
            float4 d;                                                          \
            d.x = __fadd_rn(__fmaf_rn(-2.f, lo32(Q0), sg.x), sfl);             \
            d.y = __fadd_rn(__fmaf_rn(-2.f, lo32(Q1), sg.y), sfl);             \
            d.z = __fadd_rn(__fmaf_rn(-2.f, lo32(Q2), sg.z), sfl);             \
            d.w = __fadd_rn(__fmaf_rn(-2.f, lo32(Q3), sg.w), sfl);             \
            *(float4*)(obase + (size_t)(2 * (P)) * F) = d;                     \
            d.x = __fadd_rn(__fmaf_rn(-2.f, hi32(Q0), sg.x), sfh);             \
            d.y = __fadd_rn(__fmaf_rn(-2.f, hi32(Q1), sg.y), sfh);             \
            d.z = __fadd_rn(__fmaf_rn(-2.f, hi32(Q2), sg.z), sfh);             \
            d.w = __fadd_rn(__fmaf_rn(-2.f, hi32(Q3), sg.w), sfh);             \
            *(float4*)(obase + (size_t)(2 * (P) + 1) * F) = d;                 \
        }
        FIN_PAIR(q00, q01, q02, q03, 0)
        FIN_PAIR(q10, q11, q12, q13, 1)
        FIN_PAIR(q20, q21, q22, q23, 2)
        FIN_PAIR(q30, q31, q32, q33, 3)
#undef FIN_PAIR
    }
}

// ---------------------------------------------------------------------------
// Kernel 3: per-row top-16, r12 bisection skeleton + INTERPOLATION probing
// (alternating with bisection for guaranteed convergence): ~8-12 iterations
// instead of ~26. Exact 16th-key bracketing semantics unchanged; +7 ulp
// sqrt-tie margin; smem compaction; exact (sqrt, idx) lex ranks.
// One CTA (256 threads) per row.
// ---------------------------------------------------------------------------
#define ELEMS   16              // F / 256
#define CANDMAX 128

__global__ __launch_bounds__(256) void k_select() {
    __shared__ unsigned s_mn[8], s_mx[8];
    __shared__ int s_red[8];
    __shared__ int s_cnt;
    __shared__ int s_pos;
    __shared__ int   cand[CANDMAX];
    __shared__ float cdv[CANDMAX];

    const int t   = threadIdx.x;
    const int row = blockIdx.x;
    const float* dr = g_d2 + (size_t)row * F;

    // registers: element i of thread t is row index i*256 + t (coalesced)
    unsigned u[ELEMS];
#pragma unroll
    for (int i = 0; i < ELEMS; ++i)
        u[i] = __float_as_uint(fmaxf(dr[i * 256 + t], 0.f));

    // --- block min/max of keys ---
    unsigned mn = 0xFFFFFFFFu, mx = 0u;
#pragma unroll
    for (int i = 0; i < ELEMS; ++i) { mn = min(mn, u[i]); mx = max(mx, u[i]); }
    mn = __reduce_min_sync(0xFFFFFFFFu, mn);
    mx = __reduce_max_sync(0xFFFFFFFFu, mx);
    if ((t & 31) == 0) { s_mn[t >> 5] = mn; s_mx[t >> 5] = mx; }
    __syncthreads();
    unsigned lo = s_mn[0], hi = s_mx[0];
#pragma unroll
    for (int j = 1; j < 8; ++j) { lo = min(lo, s_mn[j]); hi = max(hi, s_mx[j]); }

    // --- hybrid interpolation/bisection: smallest key T, count(u<=T) >= K ---
    // invariants: clo = count(u <= lo-1) < K <= chi = count(u <= hi)
    int chi = F, clo = 0;
    int it = 0;
    while (chi > 96 && lo < hi) {
        unsigned span = hi - lo;
        unsigned mid;
        if ((it & 1) == 0 && chi > clo) {
            // interpolation probe (clamped inside the open bracket)
            unsigned long long off =
                ((unsigned long long)span * (unsigned)(K - clo)) / (unsigned)(chi - clo);
            if (off >= span) off = span - 1;
            mid = lo + (unsigned)off;
        } else {
            mid = lo + (span >> 1);
        }
        int lc = 0;
#pragma unroll
        for (int i = 0; i < ELEMS; ++i) lc += (u[i] <= mid) ? 1 : 0;
        lc = __reduce_add_sync(0xFFFFFFFFu, lc);
        if ((t & 31) == 0) s_red[t >> 5] = lc;
        __syncthreads();
        if (t == 0) {
            int c = 0;
#pragma unroll
            for (int j = 0; j < 8; ++j) c += s_red[j];
            s_cnt = c;
        }
        __syncthreads();
        int c = s_cnt;
        if (c >= K) { hi = mid; chi = c; } else { lo = mid + 1; clo = c; }
        ++it;
    }

    // threshold: exact-or-bracketed 16th key, +7 ulp margin (sqrt-round ties)
    unsigned long long t64 = (unsigned long long)hi + 7ull;
    unsigned thr = (t64 > 0xFFFFFFFFull) ? 0xFFFFFFFFu : (unsigned)t64;

    // --- compaction (order arbitrary; ranks are order-independent) ---
    if (t == 0) s_pos = 0;
    __syncthreads();
#pragma unroll
    for (int i = 0; i < ELEMS; ++i) {
        if (u[i] <= thr) {
            int p = atomicAdd_block(&s_pos, 1);
            if (p < CANDMAX) {
                cand[p] = i * 256 + t;
                cdv[p]  = sqrtf(__uint_as_float(u[i]));
            }
        }
    }
    __syncthreads();
    int cnt = s_pos < CANDMAX ? s_pos : CANDMAX;

    // --- exact lex (d, idx) ranks in parallel; ranks are a permutation ---
    if (t < cnt) {
        float dq = cdv[t]; int gq = cand[t];
        int rank = 0;
        for (int j = 0; j < cnt; ++j) {
            rank += lexlt(cdv[j], cand[j], dq, gq) ? 1 : 0;
        }
        if (rank < K) g_cols[1 + row * K + rank] = gq;
    }
    if (row == 0 && t == 0) g_cols[0] = 0;
}

// ---------------------------------------------------------------------------
// Kernel 4: gather — FROZEN at the measured-best config (~86us):
// RB=4 rows in 64 KB smem, 256 threads, scalar __stcs stores.
// ---------------------------------------------------------------------------
#define RB 4
#define GATHER_SMEM (RB * F * 4)

__global__ __launch_bounds__(256) void k_gather(const float* __restrict__ inputs,
                                                float* __restrict__ out) {
    extern __shared__ float s_in[];   // RB * 4096
    const int b0 = blockIdx.x * RB;

    for (int idx = threadIdx.x; idx < (RB * F) / 4; idx += 256) {
        int r = idx >> 10, q = idx & 1023;
        *(float4*)(s_in + r * F + q * 4) =
            *(const float4*)(inputs + (size_t)(b0 + r) * F + q * 4);
    }
    __syncthreads();

    for (int j = threadIdx.x; j < J; j += 256) {
        int c = __ldg(&g_cols[j]);
#pragma unroll
        for (int r = 0; r < RB; ++r) {
            __stcs(out + (size_t)(b0 + r) * J + j, s_in[r * F + c]);
        }
    }
}

// ---------------------------------------------------------------------------
extern "C" void kernel_launch(void* const* d_in, const int* in_sizes, int n_in,
                              void* d_out, int out_size) {
    const float* inputs = (const float*)d_in[0];
    const float* coord  = (const float*)d_in[1];
    if (n_in >= 2 && in_sizes[0] < in_sizes[1]) {
        const float* t = inputs; inputs = coord; coord = t;
    }
    float* out = (float*)d_out;

    static bool attr_done = false;
    if (!attr_done) {
        cudaFuncSetAttribute(k_dist, cudaFuncAttributeMaxDynamicSharedMemorySize,
                             SMEM_DIST_BYTES);
        cudaFuncSetAttribute(k_gather, cudaFuncAttributeMaxDynamicSharedMemorySize,
                             GATHER_SMEM);
        attr_done = true;
    }

    k_sq<<<F / 256, 256>>>(coord);
    k_dist<<<(F / ROWS_CTA) * (F / GW), 256, SMEM_DIST_BYTES>>>(coord);
    k_select<<<F, 256>>>();
    k_gather<<<B / RB, 256, GATHER_SMEM>>>(inputs, out);
}

// round 17
// speedup vs baseline: 1.0718x; 1.0718x over previous
#include <cuda_runtime.h>
#include <cstdint>
#include <cfloat>

// Problem constants
#define F 4096      // nb_features
#define C 64        // coord dim
#define B 1024      // batch
#define K 16        // nb_neighbors
#define J (F*K + 1) // 65537 gathered columns

// Scratch (no allocations allowed; __device__ globals are the sanctioned path)
__device__ float g_sq[F];
__device__ int   g_cols[J];
__device__ float g_d2[(size_t)F * F];   // 64 MB distance-squared matrix (L2-resident)

__device__ __forceinline__ bool lexlt(float d, int g, float v, int i) {
    return (d < v) || (d == v && g < i);
}

__device__ __forceinline__ unsigned long long fma2p(unsigned long long a,
                                                    unsigned long long b,
                                                    unsigned long long c) {
    unsigned long long d;
    asm("fma.rn.f32x2 %0, %1, %2, %3;" : "=l"(d) : "l"(a), "l"(b), "l"(c));
    return d;
}
__device__ __forceinline__ float lo32(unsigned long long v) {
    return __uint_as_float((unsigned)v);
}
__device__ __forceinline__ float hi32(unsigned long long v) {
    return __uint_as_float((unsigned)(v >> 32));
}

// ---------------------------------------------------------------------------
// Kernel 1: per-feature squared norms (UNFUSED mul+add, sequential — matches
// the reference's square+reduce rounding; rel_err is exactly 0 with this).
// ---------------------------------------------------------------------------
__global__ __launch_bounds__(256) void k_sq(const float* __restrict__ coord) {
    int f = blockIdx.x * 256 + threadIdx.x;
    float s = 0.f;
#pragma unroll
    for (int c = 0; c < C; ++c) {
        float x = coord[c * F + f];
        s = __fadd_rn(s, __fmul_rn(x, x));
    }
    g_sq[f] = s;
}

// ---------------------------------------------------------------------------
// Kernel 2: PURE distance GEMM -> g_d2 — EXACT r12 winner (verified ~52us).
// ---------------------------------------------------------------------------
#define ROWS_CTA 32
#define GW       1024
#define TGG      128
#define NT       (GW / TGG)   // 8

__global__ __launch_bounds__(256) void k_dist(const float* __restrict__ coord) {
    __shared__ float s_f[C * ROWS_CTA];   // 8 KB
    __shared__ float s_sqf[ROWS_CTA];
    __shared__ float s_g[C * TGG];        // 32 KB
    __shared__ float s_sqg[TGG];

    const int tid  = threadIdx.x;
    const int lane = tid & 31;
    const int w    = tid >> 5;           // warp id: rows w*4 .. w*4+3
    const int f0   = (blockIdx.x >> 2) * ROWS_CTA;
    const int g0   = (blockIdx.x & 3) * GW;

    for (int idx = tid; idx < (C * ROWS_CTA) / 4; idx += 256) {
        int c = idx >> 3, r4 = (idx & 7) * 4;
        *(float4*)(s_f + c * ROWS_CTA + r4) = *(const float4*)(coord + c * F + f0 + r4);
    }
    if (tid < ROWS_CTA / 4)
        *(float4*)(s_sqf + tid * 4) = *(const float4*)(g_sq + f0 + tid * 4);

    for (int t = 0; t < NT; ++t) {
        const int gb = g0 + t * TGG;
        __syncthreads();
        for (int idx = tid; idx < (C * TGG) / 4; idx += 256) {
            int c = idx >> 5, o4 = (idx & 31) * 4;
            *(float4*)(s_g + c * TGG + o4) = *(const float4*)(coord + c * F + gb + o4);
        }
        if (tid < TGG / 4)
            *(float4*)(s_sqg + tid * 4) = *(const float4*)(g_sq + gb + tid * 4);
        __syncthreads();

        unsigned long long p00 = 0, p01 = 0, p10 = 0, p11 = 0;
        unsigned long long p20 = 0, p21 = 0, p30 = 0, p31 = 0;

        const float* fp = s_f + w * 4;
        const float* gp = s_g + lane * 4;
#pragma unroll 2
        for (int c = 0; c < C; ++c) {
            float4 a = *(const float4*)(fp + c * ROWS_CTA);            // 4 rows, bcast
            ulonglong2 bb = *(const ulonglong2*)(gp + c * TGG);        // g pairs
            unsigned long long ax, ay, az, aw;
            asm("mov.b64 %0,{%1,%1};" : "=l"(ax) : "r"(__float_as_uint(a.x)));
            asm("mov.b64 %0,{%1,%1};" : "=l"(ay) : "r"(__float_as_uint(a.y)));
            asm("mov.b64 %0,{%1,%1};" : "=l"(az) : "r"(__float_as_uint(a.z)));
            asm("mov.b64 %0,{%1,%1};" : "=l"(aw) : "r"(__float_as_uint(a.w)));
            p00 = fma2p(ax, bb.x, p00);  p01 = fma2p(ax, bb.y, p01);
            p10 = fma2p(ay, bb.x, p10);  p11 = fma2p(ay, bb.y, p11);
            p20 = fma2p(az, bb.x, p20);  p21 = fma2p(az, bb.y, p21);
            p30 = fma2p(aw, bb.x, p30);  p31 = fma2p(aw, bb.y, p31);
        }

        float4 sg = *(const float4*)(s_sqg + lane * 4);
        const float* sfp = s_sqf + w * 4;
        float* obase = g_d2 + (size_t)(f0 + w * 4) * F + gb + lane * 4;
#define FIN_ROW(PL, PH, R)                                                     \
        {                                                                      \
            float sf = sfp[R];                                                 \
            float4 d;                                                          \
            d.x = __fadd_rn(__fmaf_rn(-2.f, lo32(PL), sg.x), sf);              \
            d.y = __fadd_rn(__fmaf_rn(-2.f, hi32(PL), sg.y), sf);              \
            d.z = __fadd_rn(__fmaf_rn(-2.f, lo32(PH), sg.z), sf);              \
            d.w = __fadd_rn(__fmaf_rn(-2.f, hi32(PH), sg.w), sf);              \
            *(float4*)(obase + (size_t)(R) * F) = d;                           \
        }
        FIN_ROW(p00, p01, 0) FIN_ROW(p10, p11, 1)
        FIN_ROW(p20, p21, 2) FIN_ROW(p30, p31, 3)
#undef FIN_ROW
    }
}

// ---------------------------------------------------------------------------
// Kernel 3: per-row top-16 via PER-WARP bisection (barrier-free inner loop).
// Each warp bisects ITS OWN 512 elements for the warp-local 16th key
// (global top-16 is contained in the union of per-warp top-16s, since every
// warp-local 16th key >= the global 16th key). Exit at local count <= 24.
// +7 ulp margin per warp (covers sqrt-round ties; superset of the global
// margin set). Compaction + exact (sqrt, idx) lex ranks as before.
// One CTA (256 threads = 8 warps) per row; only 2 block barriers total.
// ---------------------------------------------------------------------------
#define ELEMS   16              // 512 per warp / 32 lanes
#define CANDMAX 384

__global__ __launch_bounds__(256) void k_select() {
    __shared__ int s_pos;
    __shared__ int   cand[CANDMAX];
    __shared__ float cdv[CANDMAX];

    const int t    = threadIdx.x;
    const int w    = t >> 5;
    const int lane = t & 31;
    const int row  = blockIdx.x;
    const float* dr = g_d2 + (size_t)row * F;

    if (t == 0) s_pos = 0;
    __syncthreads();   // s_pos visible before any warp's compaction

    // warp w owns elements [w*512, (w+1)*512); lane element i at i*32+lane
    const int base = w * 512;
    unsigned u[ELEMS];
#pragma unroll
    for (int i = 0; i < ELEMS; ++i)
        u[i] = __float_as_uint(fmaxf(dr[base + i * 32 + lane], 0.f));

    // --- warp min/max of keys ---
    unsigned mn = 0xFFFFFFFFu, mx = 0u;
#pragma unroll
    for (int i = 0; i < ELEMS; ++i) { mn = min(mn, u[i]); mx = max(mx, u[i]); }
    unsigned lo = __reduce_min_sync(0xFFFFFFFFu, mn);
    unsigned hi = __reduce_max_sync(0xFFFFFFFFu, mx);

    // --- warp-local bisection: smallest key T with count(u <= T) >= K ---
    // invariant: count(u <= hi) >= K (512 >= 16 initially). NO block barriers.
    int chi = 512;
    while (chi > 24 && lo < hi) {
        unsigned mid = lo + ((hi - lo) >> 1);
        int lc = 0;
#pragma unroll
        for (int i = 0; i < ELEMS; ++i) lc += (u[i] <= mid) ? 1 : 0;
        lc = __reduce_add_sync(0xFFFFFFFFu, lc);
        if (lc >= K) { hi = mid; chi = lc; } else { lo = mid + 1; }
    }

    // warp-local threshold: bracketed local 16th key, +7 ulp margin
    unsigned long long t64 = (unsigned long long)hi + 7ull;
    unsigned thr = (t64 > 0xFFFFFFFFull) ? 0xFFFFFFFFu : (unsigned)t64;

    // --- compaction (order arbitrary; ranks are order-independent) ---
#pragma unroll
    for (int i = 0; i < ELEMS; ++i) {
        if (u[i] <= thr) {
            int p = atomicAdd_block(&s_pos, 1);
            if (p < CANDMAX) {
                cand[p] = base + i * 32 + lane;
                cdv[p]  = sqrtf(__uint_as_float(u[i]));
            }
        }
    }
    __syncthreads();
    int cnt = s_pos < CANDMAX ? s_pos : CANDMAX;

    // --- exact lex (d, idx) ranks in parallel; ranks are a permutation ---
    for (int q = t; q < cnt; q += 256) {
        float dq = cdv[q]; int gq = cand[q];
        int rank = 0;
        for (int j = 0; j < cnt; ++j) {
            rank += lexlt(cdv[j], cand[j], dq, gq) ? 1 : 0;
        }
        if (rank < K) g_cols[1 + row * K + rank] = gq;
    }
    if (row == 0 && t == 0) g_cols[0] = 0;
}

// ---------------------------------------------------------------------------
// Kernel 4: gather — FROZEN at the measured-best config (~80us, write-BW
// wall): RB=4 rows in 64 KB smem, 256 threads, scalar __stcs stores.
// ---------------------------------------------------------------------------
#define RB 4
#define GATHER_SMEM (RB * F * 4)

__global__ __launch_bounds__(256) void k_gather(const float* __restrict__ inputs,
                                                float* __restrict__ out) {
    extern __shared__ float s_in[];   // RB * 4096
    const int b0 = blockIdx.x * RB;

    for (int idx = threadIdx.x; idx < (RB * F) / 4; idx += 256) {
        int r = idx >> 10, q = idx & 1023;
        *(float4*)(s_in + r * F + q * 4) =
            *(const float4*)(inputs + (size_t)(b0 + r) * F + q * 4);
    }
    __syncthreads();

    for (int j = threadIdx.x; j < J; j += 256) {
        int c = __ldg(&g_cols[j]);
#pragma unroll
        for (int r = 0; r < RB; ++r) {
            __stcs(out + (size_t)(b0 + r) * J + j, s_in[r * F + c]);
        }
    }
}

// ---------------------------------------------------------------------------
extern "C" void kernel_launch(void* const* d_in, const int* in_sizes, int n_in,
                              void* d_out, int out_size) {
    const float* inputs = (const float*)d_in[0];
    const float* coord  = (const float*)d_in[1];
    if (n_in >= 2 && in_sizes[0] < in_sizes[1]) {
        const float* t = inputs; inputs = coord; coord = t;
    }
    float* out = (float*)d_out;

    static bool attr_done = false;
    if (!attr_done) {
        cudaFuncSetAttribute(k_gather, cudaFuncAttributeMaxDynamicSharedMemorySize,
                             GATHER_SMEM);
        attr_done = true;
    }

    k_sq<<<F / 256, 256>>>(coord);
    k_dist<<<(F / ROWS_CTA) * (F / GW), 256>>>(coord);
    k_select<<<F, 256>>>();
    k_gather<<<B / RB, 256, GATHER_SMEM>>>(inputs, out);
}